// round 6
// baseline (speedup 1.0000x reference)
#include <cuda_runtime.h>
#include <cstdint>

#define N_RES   20000
#define N_EDGE  640000
#define NUM_AA  21
#define FEAT    340
#define EPSV    1e-8f
#define EPB     16         // edges (warps) per block

// ---------------- device scratch (no mallocs allowed) ----------------
__device__ float4 g_bb4[N_RES * 4];     // atoms n, ca, c, cb as float4 (w=0)
__device__ float4 g_Rt4[N_RES * 3];     // 12 floats: R[0..8], t[0..2]
__device__ float  g_local[N_RES * 12];  // R^T (bb - t)
__device__ float  g_seqf[N_RES];        // int_as_float(seq)
__device__ int    g_mask_kind;          // 0=bool(u8), 1=int32, 2=float32

__constant__ float c_freq[8] = {
    1.0f, 0.31622776601683794f, 0.1f, 0.03162277660168379f,
    0.01f, 0.0031622776601683794f, 0.001f, 0.00031622776601683794f
};

#define RBF_DELTA 1.0666666666666667f    /* (4/3)*0.8 */
#define RBF_DSQ   1.1377777777777778f    /* delta^2 */
#define RBF_C     0.10274027f            /* exp(-2*delta^2) */

// ---------------- prep: residue geometry + mask dtype detection ----------------
// Grid = 80 blocks x 256. Blocks 0..78 cover the 20000 residues; block 79 does
// mask-dtype detection with batched (MLP=19) loads.
// Detection: reads first 4864 words (= 19456 bytes, in-bounds under every
// interpretation of the 20000-element mask). int32 0/1 -> words all in {0,1};
// float32 0/1 -> words all in {0, 0x3F800000}; packed bool bytes -> neither.
// g_mask_kind is consumed only by the NEXT kernel launch (edge), so no
// intra-grid ordering is needed.
__global__ void prep_kernel(const float* __restrict__ atom14,
                            const float* __restrict__ rig,
                            const int*   __restrict__ seq,
                            const unsigned int* __restrict__ mask_w) {
    if (blockIdx.x == 79) {
        __shared__ int s_not01, s_notf;
        if (threadIdx.x == 0) { s_not01 = 0; s_notf = 0; }
        __syncthreads();
        unsigned int v[19];
        #pragma unroll
        for (int k = 0; k < 19; k++) v[k] = mask_w[threadIdx.x + 256 * k];
        int not01 = 0, notf = 0;
        #pragma unroll
        for (int k = 0; k < 19; k++) {
            if (v[k] > 1u) not01 = 1;
            if (v[k] != 0u && v[k] != 0x3F800000u) notf = 1;
        }
        if (not01) atomicOr(&s_not01, 1);
        if (notf)  atomicOr(&s_notf, 1);
        __syncthreads();
        if (threadIdx.x == 0) {
            int kind;
            if (!s_notf)       kind = 2;   // float32
            else if (!s_not01) kind = 1;   // int32
            else               kind = 0;   // bool bytes
            g_mask_kind = kind;
        }
        return;
    }

    int r = blockIdx.x * blockDim.x + threadIdx.x;
    if (r >= N_RES) return;

    const float* a = atom14 + (size_t)r * 42;   // 14 atoms * 3
    float n0 = a[0], n1 = a[1], n2 = a[2];
    float ca0 = a[3], ca1 = a[4], ca2 = a[5];
    float c0 = a[6], c1 = a[7], c2 = a[8];

    float b0 = ca0 - n0, b1 = ca1 - n1, b2 = ca2 - n2;
    float e0 = c0 - ca0, e1 = c1 - ca1, e2 = c2 - ca2;
    float ax = b1 * e2 - b2 * e1;
    float ay = b2 * e0 - b0 * e2;
    float az = b0 * e1 - b1 * e0;
    float cb0 = -0.58273431f * ax + 0.56802827f * b0 - 0.54067466f * e0 + ca0;
    float cb1 = -0.58273431f * ay + 0.56802827f * b1 - 0.54067466f * e1 + ca1;
    float cb2 = -0.58273431f * az + 0.56802827f * b2 - 0.54067466f * e2 + ca2;

    float bb[12] = { n0, n1, n2, ca0, ca1, ca2, c0, c1, c2, cb0, cb1, cb2 };
    g_bb4[r * 4 + 0] = make_float4(n0, n1, n2, 0.f);
    g_bb4[r * 4 + 1] = make_float4(ca0, ca1, ca2, 0.f);
    g_bb4[r * 4 + 2] = make_float4(c0, c1, c2, 0.f);
    g_bb4[r * 4 + 3] = make_float4(cb0, cb1, cb2, 0.f);

    const float* q = rig + (size_t)r * 7;
    float qw = q[0], qx = q[1], qy = q[2], qz = q[3];
    float inv = rsqrtf(qw * qw + qx * qx + qy * qy + qz * qz);
    qw *= inv; qx *= inv; qy *= inv; qz *= inv;

    float R[9];
    R[0] = 1.f - 2.f * (qy * qy + qz * qz);
    R[1] = 2.f * (qx * qy - qw * qz);
    R[2] = 2.f * (qx * qz + qw * qy);
    R[3] = 2.f * (qx * qy + qw * qz);
    R[4] = 1.f - 2.f * (qx * qx + qz * qz);
    R[5] = 2.f * (qy * qz - qw * qx);
    R[6] = 2.f * (qx * qz - qw * qy);
    R[7] = 2.f * (qy * qz + qw * qx);
    R[8] = 1.f - 2.f * (qx * qx + qy * qy);
    float t0 = q[4], t1 = q[5], t2 = q[6];

    g_Rt4[r * 3 + 0] = make_float4(R[0], R[1], R[2], R[3]);
    g_Rt4[r * 3 + 1] = make_float4(R[4], R[5], R[6], R[7]);
    g_Rt4[r * 3 + 2] = make_float4(R[8], t0, t1, t2);

    // local[k][i] = sum_j R[j][i] * (bb[k][j] - t[j])
    #pragma unroll
    for (int k = 0; k < 4; k++) {
        float vx = bb[k * 3 + 0] - t0;
        float vy = bb[k * 3 + 1] - t1;
        float vz = bb[k * 3 + 2] - t2;
        #pragma unroll
        for (int i = 0; i < 3; i++) {
            g_local[r * 12 + k * 3 + i] = R[0 + i] * vx + R[3 + i] * vy + R[6 + i] * vz;
        }
    }

    g_seqf[r] = __int_as_float(seq[r]);
}

// ---------------- per-edge feature kernel: 1 warp / edge, direct-to-GMEM ----------------
__global__ __launch_bounds__(EPB * 32) void edge_kernel(
    const int* __restrict__ eidx,     // [2, N_EDGE]: row0=dst, row1=src
    const void* __restrict__ mask,
    float* __restrict__ out) {

    __shared__ float4 sstage4[EPB][7];

    int w    = threadIdx.x >> 5;
    int lane = threadIdx.x & 31;
    int e    = blockIdx.x * EPB + w;

    int dst = eidx[e];
    int src = eidx[N_EDGE + e];

    // ---- issue ALL gathers up front (max MLP; tables are L2-resident) ----
    float4 f4s = g_bb4[src * 4 + ((lane >> 2) & 3)];   // src atom i (lanes 0-15)
    float4 f4d = g_bb4[dst * 4 + (lane & 3)];          // dst atom j
    int c = min(max(lane - 4, 0), 2);
    float4 f4rt = g_Rt4[src * 3 + c];                  // R/t chunk (lanes 4-6)
    float seqs = g_seqf[src];
    float seqd = g_seqf[dst];
    float loc  = g_local[src * 12 + min(lane, 11)];    // lanes 0-11 meaningful

    int kind = g_mask_kind;                            // grid-uniform branch
    float noised_src, noised_dst;
    if (kind == 0) {
        noised_src = ((const unsigned char*)mask)[src] ? 1.f : 0.f;
        noised_dst = ((const unsigned char*)mask)[dst] ? 1.f : 0.f;
    } else if (kind == 1) {
        noised_src = ((const int*)mask)[src] ? 1.f : 0.f;
        noised_dst = ((const int*)mask)[dst] ? 1.f : 0.f;
    } else {
        noised_src = (((const float*)mask)[src] != 0.f) ? 1.f : 0.f;
        noised_dst = (((const float*)mask)[dst] != 0.f) ? 1.f : 0.f;
    }
    float keep_src = 1.f - noised_src;
    float keep_dst = 1.f - noised_dst;
    int hot_src = __float_as_int(seqs) + 2;    // one-hot pos within row, [2,22]
    int hot_dst = __float_as_int(seqd) + 23;   // one-hot pos within row, [23,43]

    // stage: floats [0..15] = bb_dst atoms (xyzw), [16..24] = R, [25..27] = t
    float* st = (float*)sstage4[w];
    if (lane < 4)               sstage4[w][lane] = f4d;
    if (lane >= 4 && lane < 7)  sstage4[w][lane] = f4rt;
    __syncwarp();

    // ---- distances + both RBF broadcasts before any store ----
    float dx = f4s.x - f4d.x + EPSV;
    float dy = f4s.y - f4d.y + EPSV;
    float dz = f4s.z - f4d.z + EPSV;
    float D = sqrtf(dx * dx + dy * dy + dz * dz);
    float Da = __shfl_sync(0xFFFFFFFFu, D, lane >> 2);
    float Db = __shfl_sync(0xFFFFFFFFu, D, 8 + (lane >> 2));

    float* __restrict__ row = out + (size_t)e * FEAT;

    // ---- region B math: geometric recurrence, 2 MUFU + 6 FMUL per sweep ----
    float mu0 = 2.0f + (float)(4 * (lane & 3)) * (20.0f / 15.0f);
    float za = (Da - mu0) * 0.8f;
    float ra0 = __expf(-za * za);
    float ga  = __expf(fminf(2.0f * RBF_DELTA * za - RBF_DSQ, 80.f));
    float ra1 = ra0 * ga; ga *= RBF_C;
    float ra2 = ra1 * ga; ga *= RBF_C;
    float ra3 = ra2 * ga;

    float zb = (Db - mu0) * 0.8f;
    float rb0 = __expf(-zb * zb);
    float gb  = __expf(fminf(2.0f * RBF_DELTA * zb - RBF_DSQ, 80.f));
    float rb1 = rb0 * gb; gb *= RBF_C;
    float rb2 = rb1 * gb; gb *= RBF_C;
    float rb3 = rb2 * gb;

    // ---- region A: [0..43] flags + one-hots, 11 lanes x STG.128 ----
    if (lane < 11) {
        float4 v4;
        float* vp = &v4.x;
        #pragma unroll
        for (int cc = 0; cc < 4; cc++) {
            int idx = 4 * lane + cc;
            float x = (idx == hot_src) ? keep_src : 0.f;
            x = (idx == hot_dst) ? keep_dst : x;
            vp[cc] = x;
        }
        if (lane == 0) { v4.x = noised_dst; v4.y = noised_src; }
        __stcs((float4*)(row + 4 * lane), v4);
    }

    // ---- region B stores: dense [44..171] and [172..299] ----
    __stcs((float4*)(row + 44  + 4 * lane), make_float4(ra0, ra1, ra2, ra3));
    __stcs((float4*)(row + 172 + 4 * lane), make_float4(rb0, rb1, rb2, rb3));

    // ---- region C: [300..315] positional enc (fast sin/cos, HW range red.) ----
    if (lane < 16) {
        float dp = (float)(dst - src);
        float ang = dp * c_freq[lane & 7];
        __stcs(row + 300 + lane, (lane < 8) ? __cosf(ang) : __sinf(ang));
    }

    // ---- regions D+E fused: [316..339] one predicated STG over 24 lanes ----
    if (lane < 24) {
        float v;
        if (lane < 12) {
            v = loc * keep_src;
        } else {
            int l = lane - 12;
            int kk = l / 3, ii = l - kk * 3;
            float acc = 0.f;
            #pragma unroll
            for (int jj = 0; jj < 3; jj++)
                acc += st[16 + jj * 3 + ii] * (st[kk * 4 + jj] - st[25 + jj]);
            v = acc * keep_dst;
        }
        __stcs(row + 316 + lane, v);
    }
}

// ---------------- launch ----------------
extern "C" void kernel_launch(void* const* d_in, const int* in_sizes, int n_in,
                              void* d_out, int out_size) {
    const float* atom14 = (const float*)d_in[0];
    const float* rigids = (const float*)d_in[1];
    const int*   seq    = (const int*)d_in[2];
    const void*  mask   = d_in[3];
    const int*   eidx   = (const int*)d_in[4];
    float* out = (float*)d_out;

    prep_kernel<<<80, 256>>>(atom14, rigids, seq, (const unsigned int*)mask);
    edge_kernel<<<N_EDGE / EPB, EPB * 32>>>(eidx, mask, out);
}

// round 7
// speedup vs baseline: 1.6710x; 1.6710x over previous
#include <cuda_runtime.h>
#include <cstdint>

#define N_RES   20000
#define N_EDGE  640000
#define NUM_AA  21
#define FEAT    340
#define EPSV    1e-8f
#define EPB     8          // edges (warps) per block

// ---------------- device scratch (no mallocs allowed) ----------------
__device__ float4 g_bb4[N_RES * 4];     // atoms n, ca, c, cb as float4 (w=0)
__device__ float4 g_Rt4[N_RES * 3];     // 12 floats: R[0..8], t[0..2]
__device__ float  g_local[N_RES * 12];  // R^T (bb - t)
__device__ float2 g_meta[N_RES];        // (noised, int_as_float(seq))
__device__ int    g_mask_kind;          // 0=bool(u8), 1=int32, 2=float32

__constant__ float c_freq[8] = {
    1.0f, 0.31622776601683794f, 0.1f, 0.03162277660168379f,
    0.01f, 0.0031622776601683794f, 0.001f, 0.00031622776601683794f
};

#define RBF_DELTA 1.0666666666666667f    /* (4/3)*0.8 */
#define RBF_DSQ   1.1377777777777778f    /* delta^2 */
#define RBF_C     0.10274027f            /* exp(-2*delta^2) */

// ---------------- mask dtype detection (1 block, batched MLP-19 loads) ----------------
// Reads first 4864 words (= 19456 bytes, in-bounds under every interpretation
// of the 20000-element mask). int32 0/1 -> words all in {0,1}; float32 0/1 ->
// words all in {0, 0x3F800000}; packed bool bytes -> neither.
__global__ void detect_kernel(const unsigned int* __restrict__ mask_w) {
    __shared__ int s_not01, s_notf;
    if (threadIdx.x == 0) { s_not01 = 0; s_notf = 0; }
    __syncthreads();
    unsigned int v[19];
    #pragma unroll
    for (int k = 0; k < 19; k++) v[k] = mask_w[threadIdx.x + 256 * k];
    int not01 = 0, notf = 0;
    #pragma unroll
    for (int k = 0; k < 19; k++) {
        if (v[k] > 1u) not01 = 1;
        if (v[k] != 0u && v[k] != 0x3F800000u) notf = 1;
    }
    if (not01) atomicOr(&s_not01, 1);
    if (notf)  atomicOr(&s_notf, 1);
    __syncthreads();
    if (threadIdx.x == 0) {
        int kind;
        if (!s_notf)       kind = 2;   // float32
        else if (!s_not01) kind = 1;   // int32
        else               kind = 0;   // bool bytes
        g_mask_kind = kind;
    }
}

// ---------------- prep: residue geometry + packed metadata ----------------
__global__ void prep_kernel(const float* __restrict__ atom14,
                            const float* __restrict__ rig,
                            const int*   __restrict__ seq,
                            const void*  __restrict__ mask) {
    int r = blockIdx.x * blockDim.x + threadIdx.x;
    if (r >= N_RES) return;

    const float* a = atom14 + (size_t)r * 42;   // 14 atoms * 3
    float n0 = a[0], n1 = a[1], n2 = a[2];
    float ca0 = a[3], ca1 = a[4], ca2 = a[5];
    float c0 = a[6], c1 = a[7], c2 = a[8];

    float b0 = ca0 - n0, b1 = ca1 - n1, b2 = ca2 - n2;
    float e0 = c0 - ca0, e1 = c1 - ca1, e2 = c2 - ca2;
    float ax = b1 * e2 - b2 * e1;
    float ay = b2 * e0 - b0 * e2;
    float az = b0 * e1 - b1 * e0;
    float cb0 = -0.58273431f * ax + 0.56802827f * b0 - 0.54067466f * e0 + ca0;
    float cb1 = -0.58273431f * ay + 0.56802827f * b1 - 0.54067466f * e1 + ca1;
    float cb2 = -0.58273431f * az + 0.56802827f * b2 - 0.54067466f * e2 + ca2;

    float bb[12] = { n0, n1, n2, ca0, ca1, ca2, c0, c1, c2, cb0, cb1, cb2 };
    g_bb4[r * 4 + 0] = make_float4(n0, n1, n2, 0.f);
    g_bb4[r * 4 + 1] = make_float4(ca0, ca1, ca2, 0.f);
    g_bb4[r * 4 + 2] = make_float4(c0, c1, c2, 0.f);
    g_bb4[r * 4 + 3] = make_float4(cb0, cb1, cb2, 0.f);

    const float* q = rig + (size_t)r * 7;
    float qw = q[0], qx = q[1], qy = q[2], qz = q[3];
    float inv = rsqrtf(qw * qw + qx * qx + qy * qy + qz * qz);
    qw *= inv; qx *= inv; qy *= inv; qz *= inv;

    float R[9];
    R[0] = 1.f - 2.f * (qy * qy + qz * qz);
    R[1] = 2.f * (qx * qy - qw * qz);
    R[2] = 2.f * (qx * qz + qw * qy);
    R[3] = 2.f * (qx * qy + qw * qz);
    R[4] = 1.f - 2.f * (qx * qx + qz * qz);
    R[5] = 2.f * (qy * qz - qw * qx);
    R[6] = 2.f * (qx * qz - qw * qy);
    R[7] = 2.f * (qy * qz + qw * qx);
    R[8] = 1.f - 2.f * (qx * qx + qy * qy);
    float t0 = q[4], t1 = q[5], t2 = q[6];

    g_Rt4[r * 3 + 0] = make_float4(R[0], R[1], R[2], R[3]);
    g_Rt4[r * 3 + 1] = make_float4(R[4], R[5], R[6], R[7]);
    g_Rt4[r * 3 + 2] = make_float4(R[8], t0, t1, t2);

    // local[k][i] = sum_j R[j][i] * (bb[k][j] - t[j])
    #pragma unroll
    for (int k = 0; k < 4; k++) {
        float vx = bb[k * 3 + 0] - t0;
        float vy = bb[k * 3 + 1] - t1;
        float vz = bb[k * 3 + 2] - t2;
        #pragma unroll
        for (int i = 0; i < 3; i++) {
            g_local[r * 12 + k * 3 + i] = R[0 + i] * vx + R[3 + i] * vy + R[6 + i] * vz;
        }
    }

    int kind = g_mask_kind;
    float noised;
    if (kind == 0)      noised = ((const unsigned char*)mask)[r] ? 1.f : 0.f;
    else if (kind == 1) noised = ((const int*)mask)[r] ? 1.f : 0.f;
    else                noised = (((const float*)mask)[r] != 0.f) ? 1.f : 0.f;
    g_meta[r] = make_float2(noised, __int_as_float(seq[r]));
}

// ---------------- per-edge feature kernel: 1 warp / edge, direct-to-GMEM ----------------
__global__ __launch_bounds__(EPB * 32) void edge_kernel(
    const int* __restrict__ eidx,     // [2, N_EDGE]: row0=dst, row1=src
    float* __restrict__ out) {

    __shared__ float4 sstage4[EPB][7];

    int w    = threadIdx.x >> 5;
    int lane = threadIdx.x & 31;
    int e    = blockIdx.x * EPB + w;

    int dst = eidx[e];
    int src = eidx[N_EDGE + e];

    // register gathers (broadcast-heavy, L2-resident tables)
    float4 f4s = g_bb4[src * 4 + ((lane >> 2) & 3)];   // src atom i (lanes 0-15)
    float4 f4d = g_bb4[dst * 4 + (lane & 3)];          // dst atom j
    int c = min(max(lane - 4, 0), 2);
    float4 f4rt = g_Rt4[src * 3 + c];                  // R/t chunk (lanes 4-6)
    float2 ms = g_meta[src];
    float2 md = g_meta[dst];
    float loc = g_local[src * 12 + min(lane, 11)];     // lanes 0-11 meaningful

    // stage: floats [0..15] = bb_dst atoms (xyzw), [16..24] = R, [25..27] = t
    float* st = (float*)sstage4[w];
    if (lane < 4)               sstage4[w][lane] = f4d;
    if (lane >= 4 && lane < 7)  sstage4[w][lane] = f4rt;
    __syncwarp();

    float noised_src = ms.x, noised_dst = md.x;
    float keep_src = 1.f - noised_src;
    float keep_dst = 1.f - noised_dst;
    int hot_src = __float_as_int(ms.y) + 2;    // one-hot pos within row, [2,22]
    int hot_dst = __float_as_int(md.y) + 23;   // one-hot pos within row, [23,43]

    float* __restrict__ row = out + (size_t)e * FEAT;

    // ---- region A: [0..43] flags + one-hots, 11 lanes x STG.128 ----
    if (lane < 11) {
        float4 v4;
        float* vp = &v4.x;
        #pragma unroll
        for (int cc = 0; cc < 4; cc++) {
            int idx = 4 * lane + cc;
            float x = (idx == hot_src) ? keep_src : 0.f;
            x = (idx == hot_dst) ? keep_dst : x;
            vp[cc] = x;
        }
        if (lane == 0) { v4.x = noised_dst; v4.y = noised_src; }
        __stcs((float4*)(row + 4 * lane), v4);
    }

    // ---- region B: [44..299] RBF of 16 dists, 16 bins each ----
    // lanes 0-15 hold src atom (lane>>2) and dst atom (lane&3) in registers:
    // each computes its distance (MUFU.RSQ fast path); two dense STG.128
    // sweeps cover [44..171] and [172..299]. Bins via geometric recurrence.
    float dx = f4s.x - f4d.x + EPSV;
    float dy = f4s.y - f4d.y + EPSV;
    float dz = f4s.z - f4d.z + EPSV;
    float d2 = dx * dx + dy * dy + dz * dz;
    float D = rsqrtf(d2) * d2;              // sqrt via MUFU.RSQ + FMUL

    float mu0 = 2.0f + (float)(4 * (lane & 3)) * (20.0f / 15.0f);
    {
        // sweep 1: lane L -> floats [44+4L..47+4L], pair = L>>2, bins 4*(L&3)..+3
        float Da = __shfl_sync(0xFFFFFFFFu, D, lane >> 2);
        float z0 = (Da - mu0) * 0.8f;
        float r0 = __expf(-z0 * z0);
        float g  = __expf(fminf(2.0f * RBF_DELTA * z0 - RBF_DSQ, 80.f));
        float r1 = r0 * g; g *= RBF_C;
        float r2 = r1 * g; g *= RBF_C;
        float r3 = r2 * g;
        __stcs((float4*)(row + 44 + 4 * lane), make_float4(r0, r1, r2, r3));

        // sweep 2: lane L -> floats [172+4L..175+4L], pair = 8 + (L>>2)
        float Db = __shfl_sync(0xFFFFFFFFu, D, 8 + (lane >> 2));
        z0 = (Db - mu0) * 0.8f;
        r0 = __expf(-z0 * z0);
        g  = __expf(fminf(2.0f * RBF_DELTA * z0 - RBF_DSQ, 80.f));
        r1 = r0 * g; g *= RBF_C;
        r2 = r1 * g; g *= RBF_C;
        r3 = r2 * g;
        __stcs((float4*)(row + 172 + 4 * lane), make_float4(r0, r1, r2, r3));
    }

    // ---- region C: [300..315] positional enc (fast sin/cos, HW range red.) ----
    if (lane < 16) {
        float dp = (float)(dst - src);
        float ang = dp * c_freq[lane & 7];
        __stcs(row + 300 + lane, (lane < 8) ? __cosf(ang) : __sinf(ang));
    }

    // ---- regions D+E fused: [316..339] one predicated STG over 24 lanes ----
    // lanes 0..11:  src local frame (prefetched) * keep_src
    // lanes 12..23: dst backbone in src frame * keep_dst
    if (lane < 24) {
        float v;
        if (lane < 12) {
            v = loc * keep_src;
        } else {
            int l = lane - 12;
            int kk = l / 3, ii = l - kk * 3;
            float acc = 0.f;
            #pragma unroll
            for (int jj = 0; jj < 3; jj++)
                acc += st[16 + jj * 3 + ii] * (st[kk * 4 + jj] - st[25 + jj]);
            v = acc * keep_dst;
        }
        __stcs(row + 316 + lane, v);
    }
}

// ---------------- launch ----------------
extern "C" void kernel_launch(void* const* d_in, const int* in_sizes, int n_in,
                              void* d_out, int out_size) {
    const float* atom14 = (const float*)d_in[0];
    const float* rigids = (const float*)d_in[1];
    const int*   seq    = (const int*)d_in[2];
    const void*  mask   = d_in[3];
    const int*   eidx   = (const int*)d_in[4];
    float* out = (float*)d_out;

    detect_kernel<<<1, 256>>>((const unsigned int*)mask);
    prep_kernel<<<(N_RES + 255) / 256, 256>>>(atom14, rigids, seq, mask);
    edge_kernel<<<N_EDGE / EPB, EPB * 32>>>(eidx, out);
}

// round 8
// speedup vs baseline: 1.6986x; 1.0165x over previous
#include <cuda_runtime.h>
#include <cstdint>

#define N_RES   20000
#define N_EDGE  640000
#define NUM_AA  21
#define FEAT    340
#define EPSV    1e-8f
#define EPB     8          // edges (warps) per block

// ---------------- device scratch (no mallocs allowed) ----------------
__device__ float4 g_bb4[N_RES * 4];     // atoms n, ca, c, cb as float4 (w=0)
__device__ float4 g_Rt4[N_RES * 3];     // 12 floats: R[0..8], t[0..2]
__device__ float  g_local[N_RES * 12];  // R^T (bb - t)
__device__ float2 g_meta[N_RES];        // (noised, int_as_float(seq))

__constant__ float c_freq[8] = {
    1.0f, 0.31622776601683794f, 0.1f, 0.03162277660168379f,
    0.01f, 0.0031622776601683794f, 0.001f, 0.00031622776601683794f
};

#define RBF_DELTA 1.0666666666666667f    /* (4/3)*0.8 */
#define RBF_DSQ   1.1377777777777778f    /* delta^2 */
#define RBF_C     0.10274027f            /* exp(-2*delta^2) */

// ---------------- prep: per-block mask dtype detection + residue geometry ----------------
// Mask dtype detection happens per-block from the first 512 words (= 2048
// bytes, in-bounds under every interpretation of the 20000-element mask):
//   int32 0/1 mask  -> words all in {0,1}
//   float32 0/1 mask-> words all in {0, 0x3F800000}
//   packed bool     -> neither (P(512 words all look like 0/1) = 8^-512 ~ 0)
// All blocks compute the same answer; block 0 warms L2 for the rest.
__global__ void prep_kernel(const float* __restrict__ atom14,
                            const float* __restrict__ rig,
                            const int*   __restrict__ seq,
                            const void*  __restrict__ mask) {
    __shared__ int s_not01, s_notf;
    if (threadIdx.x == 0) { s_not01 = 0; s_notf = 0; }
    __syncthreads();
    {
        const unsigned int* mw = (const unsigned int*)mask;
        unsigned int v0 = mw[threadIdx.x];
        unsigned int v1 = mw[threadIdx.x + 256];
        int not01 = (v0 > 1u) | (v1 > 1u);
        int notf  = ((v0 != 0u && v0 != 0x3F800000u) ||
                     (v1 != 0u && v1 != 0x3F800000u));
        if (not01) atomicOr(&s_not01, 1);
        if (notf)  atomicOr(&s_notf, 1);
    }
    __syncthreads();
    int kind;                                // 0=bool(u8), 1=int32, 2=float32
    if (!s_notf)       kind = 2;
    else if (!s_not01) kind = 1;
    else               kind = 0;

    int r = blockIdx.x * blockDim.x + threadIdx.x;
    if (r >= N_RES) return;

    const float* a = atom14 + (size_t)r * 42;   // 14 atoms * 3
    float n0 = a[0], n1 = a[1], n2 = a[2];
    float ca0 = a[3], ca1 = a[4], ca2 = a[5];
    float c0 = a[6], c1 = a[7], c2 = a[8];

    float b0 = ca0 - n0, b1 = ca1 - n1, b2 = ca2 - n2;
    float e0 = c0 - ca0, e1 = c1 - ca1, e2 = c2 - ca2;
    float ax = b1 * e2 - b2 * e1;
    float ay = b2 * e0 - b0 * e2;
    float az = b0 * e1 - b1 * e0;
    float cb0 = -0.58273431f * ax + 0.56802827f * b0 - 0.54067466f * e0 + ca0;
    float cb1 = -0.58273431f * ay + 0.56802827f * b1 - 0.54067466f * e1 + ca1;
    float cb2 = -0.58273431f * az + 0.56802827f * b2 - 0.54067466f * e2 + ca2;

    float bb[12] = { n0, n1, n2, ca0, ca1, ca2, c0, c1, c2, cb0, cb1, cb2 };
    g_bb4[r * 4 + 0] = make_float4(n0, n1, n2, 0.f);
    g_bb4[r * 4 + 1] = make_float4(ca0, ca1, ca2, 0.f);
    g_bb4[r * 4 + 2] = make_float4(c0, c1, c2, 0.f);
    g_bb4[r * 4 + 3] = make_float4(cb0, cb1, cb2, 0.f);

    const float* q = rig + (size_t)r * 7;
    float qw = q[0], qx = q[1], qy = q[2], qz = q[3];
    float inv = rsqrtf(qw * qw + qx * qx + qy * qy + qz * qz);
    qw *= inv; qx *= inv; qy *= inv; qz *= inv;

    float R[9];
    R[0] = 1.f - 2.f * (qy * qy + qz * qz);
    R[1] = 2.f * (qx * qy - qw * qz);
    R[2] = 2.f * (qx * qz + qw * qy);
    R[3] = 2.f * (qx * qy + qw * qz);
    R[4] = 1.f - 2.f * (qx * qx + qz * qz);
    R[5] = 2.f * (qy * qz - qw * qx);
    R[6] = 2.f * (qx * qz - qw * qy);
    R[7] = 2.f * (qy * qz + qw * qx);
    R[8] = 1.f - 2.f * (qx * qx + qy * qy);
    float t0 = q[4], t1 = q[5], t2 = q[6];

    g_Rt4[r * 3 + 0] = make_float4(R[0], R[1], R[2], R[3]);
    g_Rt4[r * 3 + 1] = make_float4(R[4], R[5], R[6], R[7]);
    g_Rt4[r * 3 + 2] = make_float4(R[8], t0, t1, t2);

    // local[k][i] = sum_j R[j][i] * (bb[k][j] - t[j])
    #pragma unroll
    for (int k = 0; k < 4; k++) {
        float vx = bb[k * 3 + 0] - t0;
        float vy = bb[k * 3 + 1] - t1;
        float vz = bb[k * 3 + 2] - t2;
        #pragma unroll
        for (int i = 0; i < 3; i++) {
            g_local[r * 12 + k * 3 + i] = R[0 + i] * vx + R[3 + i] * vy + R[6 + i] * vz;
        }
    }

    float noised;
    if (kind == 0)      noised = ((const unsigned char*)mask)[r] ? 1.f : 0.f;
    else if (kind == 1) noised = ((const int*)mask)[r] ? 1.f : 0.f;
    else                noised = (((const float*)mask)[r] != 0.f) ? 1.f : 0.f;
    g_meta[r] = make_float2(noised, __int_as_float(seq[r]));
}

// ---------------- per-edge feature kernel: 1 warp / edge, direct-to-GMEM ----------------
__global__ __launch_bounds__(EPB * 32) void edge_kernel(
    const int* __restrict__ eidx,     // [2, N_EDGE]: row0=dst, row1=src
    float* __restrict__ out) {

    __shared__ float4 sstage4[EPB][7];

    int w    = threadIdx.x >> 5;
    int lane = threadIdx.x & 31;
    int e    = blockIdx.x * EPB + w;

    int dst = eidx[e];
    int src = eidx[N_EDGE + e];

    // register gathers (broadcast-heavy, L2-resident tables)
    float4 f4s = g_bb4[src * 4 + ((lane >> 2) & 3)];   // src atom i (lanes 0-15)
    float4 f4d = g_bb4[dst * 4 + (lane & 3)];          // dst atom j
    int c = min(max(lane - 4, 0), 2);
    float4 f4rt = g_Rt4[src * 3 + c];                  // R/t chunk (lanes 4-6)
    float2 ms = g_meta[src];
    float2 md = g_meta[dst];
    float loc = g_local[src * 12 + min(lane, 11)];     // lanes 0-11 meaningful

    // stage: floats [0..15] = bb_dst atoms (xyzw), [16..24] = R, [25..27] = t
    float* st = (float*)sstage4[w];
    if (lane < 4)               sstage4[w][lane] = f4d;
    if (lane >= 4 && lane < 7)  sstage4[w][lane] = f4rt;
    __syncwarp();

    float noised_src = ms.x, noised_dst = md.x;
    float keep_src = 1.f - noised_src;
    float keep_dst = 1.f - noised_dst;
    int hot_src = __float_as_int(ms.y) + 2;    // one-hot pos within row, [2,22]
    int hot_dst = __float_as_int(md.y) + 23;   // one-hot pos within row, [23,43]

    float* __restrict__ row = out + (size_t)e * FEAT;

    // ---- region A: [0..43] flags + one-hots, 11 lanes x STG.128 ----
    if (lane < 11) {
        float4 v4;
        float* vp = &v4.x;
        #pragma unroll
        for (int cc = 0; cc < 4; cc++) {
            int idx = 4 * lane + cc;
            float x = (idx == hot_src) ? keep_src : 0.f;
            x = (idx == hot_dst) ? keep_dst : x;
            vp[cc] = x;
        }
        if (lane == 0) { v4.x = noised_dst; v4.y = noised_src; }
        __stcs((float4*)(row + 4 * lane), v4);
    }

    // ---- region B: [44..299] RBF of 16 dists, 16 bins each ----
    // lanes 0-15 hold src atom (lane>>2) and dst atom (lane&3) in registers:
    // each computes its distance (MUFU.RSQ fast path); two dense STG.128
    // sweeps cover [44..171] and [172..299]. Bins via geometric recurrence.
    float dx = f4s.x - f4d.x + EPSV;
    float dy = f4s.y - f4d.y + EPSV;
    float dz = f4s.z - f4d.z + EPSV;
    float d2 = dx * dx + dy * dy + dz * dz;
    float D = rsqrtf(d2) * d2;              // sqrt via MUFU.RSQ + FMUL

    float mu0 = 2.0f + (float)(4 * (lane & 3)) * (20.0f / 15.0f);
    {
        // sweep 1: lane L -> floats [44+4L..47+4L], pair = L>>2, bins 4*(L&3)..+3
        float Da = __shfl_sync(0xFFFFFFFFu, D, lane >> 2);
        float z0 = (Da - mu0) * 0.8f;
        float r0 = __expf(-z0 * z0);
        float g  = __expf(fminf(2.0f * RBF_DELTA * z0 - RBF_DSQ, 80.f));
        float r1 = r0 * g; g *= RBF_C;
        float r2 = r1 * g; g *= RBF_C;
        float r3 = r2 * g;
        __stcs((float4*)(row + 44 + 4 * lane), make_float4(r0, r1, r2, r3));

        // sweep 2: lane L -> floats [172+4L..175+4L], pair = 8 + (L>>2)
        float Db = __shfl_sync(0xFFFFFFFFu, D, 8 + (lane >> 2));
        z0 = (Db - mu0) * 0.8f;
        r0 = __expf(-z0 * z0);
        g  = __expf(fminf(2.0f * RBF_DELTA * z0 - RBF_DSQ, 80.f));
        r1 = r0 * g; g *= RBF_C;
        r2 = r1 * g; g *= RBF_C;
        r3 = r2 * g;
        __stcs((float4*)(row + 172 + 4 * lane), make_float4(r0, r1, r2, r3));
    }

    // ---- region C: [300..315] positional enc (fast sin/cos, HW range red.) ----
    if (lane < 16) {
        float dp = (float)(dst - src);
        float ang = dp * c_freq[lane & 7];
        __stcs(row + 300 + lane, (lane < 8) ? __cosf(ang) : __sinf(ang));
    }

    // ---- regions D+E fused: [316..339] one predicated STG over 24 lanes ----
    // lanes 0..11:  src local frame (prefetched) * keep_src
    // lanes 12..23: dst backbone in src frame * keep_dst
    if (lane < 24) {
        float v;
        if (lane < 12) {
            v = loc * keep_src;
        } else {
            int l = lane - 12;
            int kk = l / 3, ii = l - kk * 3;
            float acc = 0.f;
            #pragma unroll
            for (int jj = 0; jj < 3; jj++)
                acc += st[16 + jj * 3 + ii] * (st[kk * 4 + jj] - st[25 + jj]);
            v = acc * keep_dst;
        }
        __stcs(row + 316 + lane, v);
    }
}

// ---------------- launch ----------------
extern "C" void kernel_launch(void* const* d_in, const int* in_sizes, int n_in,
                              void* d_out, int out_size) {
    const float* atom14 = (const float*)d_in[0];
    const float* rigids = (const float*)d_in[1];
    const int*   seq    = (const int*)d_in[2];
    const void*  mask   = d_in[3];
    const int*   eidx   = (const int*)d_in[4];
    float* out = (float*)d_out;

    prep_kernel<<<(N_RES + 255) / 256, 256>>>(atom14, rigids, seq, mask);
    edge_kernel<<<N_EDGE / EPB, EPB * 32>>>(eidx, out);
}

// round 9
// speedup vs baseline: 1.8965x; 1.1165x over previous
#include <cuda_runtime.h>
#include <cstdint>

#define N_RES   20000
#define N_EDGE  640000
#define NUM_AA  21
#define FEAT    340
#define EPSV    1e-8f
#define EPB     8          // edges (warps) per block

// ---------------- device scratch (no mallocs allowed) ----------------
// g_bb4[r*4+k] = atom k (n,ca,c,cb); w-lanes carry metadata:
//   atom0.w = noised flag (0/1), atom1.w = int_as_float(seq)
__device__ float4 g_bb4[N_RES * 4];
// g_Rt4[r*4+c], c=0..2: column c of R = (R[0,c], R[1,c], R[2,c], 0)
//               c=3:    (t0, t1, t2, 0)
__device__ float4 g_Rt4[N_RES * 4];
__device__ float  g_local[N_RES * 12];  // R^T (bb - t)

__constant__ float c_freq[8] = {
    1.0f, 0.31622776601683794f, 0.1f, 0.03162277660168379f,
    0.01f, 0.0031622776601683794f, 0.001f, 0.00031622776601683794f
};

#define RBF_DELTA 1.0666666666666667f    /* (4/3)*0.8 */
#define RBF_DSQ   1.1377777777777778f    /* delta^2 */
#define RBF_C     0.10274027f            /* exp(-2*delta^2) */

// ---------------- prep: per-block mask dtype detection + residue geometry ----------------
// Mask dtype detection per-block from the first 512 words (= 2048 bytes,
// in-bounds under every interpretation of the 20000-element mask):
//   int32 0/1 mask   -> words all in {0,1}
//   float32 0/1 mask -> words all in {0, 0x3F800000}
//   packed bool      -> neither (P(ambiguous) = 8^-512 ~ 0)
__global__ void prep_kernel(const float* __restrict__ atom14,
                            const float* __restrict__ rig,
                            const int*   __restrict__ seq,
                            const void*  __restrict__ mask) {
    __shared__ int s_not01, s_notf;
    if (threadIdx.x == 0) { s_not01 = 0; s_notf = 0; }
    __syncthreads();
    {
        const unsigned int* mw = (const unsigned int*)mask;
        unsigned int v0 = mw[threadIdx.x];
        unsigned int v1 = mw[threadIdx.x + 256];
        int not01 = (v0 > 1u) | (v1 > 1u);
        int notf  = ((v0 != 0u && v0 != 0x3F800000u) ||
                     (v1 != 0u && v1 != 0x3F800000u));
        if (not01) atomicOr(&s_not01, 1);
        if (notf)  atomicOr(&s_notf, 1);
    }
    __syncthreads();
    int kind;                                // 0=bool(u8), 1=int32, 2=float32
    if (!s_notf)       kind = 2;
    else if (!s_not01) kind = 1;
    else               kind = 0;

    int r = blockIdx.x * blockDim.x + threadIdx.x;
    if (r >= N_RES) return;

    const float* a = atom14 + (size_t)r * 42;   // 14 atoms * 3
    float n0 = a[0], n1 = a[1], n2 = a[2];
    float ca0 = a[3], ca1 = a[4], ca2 = a[5];
    float c0 = a[6], c1 = a[7], c2 = a[8];

    float b0 = ca0 - n0, b1 = ca1 - n1, b2 = ca2 - n2;
    float e0 = c0 - ca0, e1 = c1 - ca1, e2 = c2 - ca2;
    float ax = b1 * e2 - b2 * e1;
    float ay = b2 * e0 - b0 * e2;
    float az = b0 * e1 - b1 * e0;
    float cb0 = -0.58273431f * ax + 0.56802827f * b0 - 0.54067466f * e0 + ca0;
    float cb1 = -0.58273431f * ay + 0.56802827f * b1 - 0.54067466f * e1 + ca1;
    float cb2 = -0.58273431f * az + 0.56802827f * b2 - 0.54067466f * e2 + ca2;

    float noised;
    if (kind == 0)      noised = ((const unsigned char*)mask)[r] ? 1.f : 0.f;
    else if (kind == 1) noised = ((const int*)mask)[r] ? 1.f : 0.f;
    else                noised = (((const float*)mask)[r] != 0.f) ? 1.f : 0.f;

    float bb[12] = { n0, n1, n2, ca0, ca1, ca2, c0, c1, c2, cb0, cb1, cb2 };
    g_bb4[r * 4 + 0] = make_float4(n0, n1, n2, noised);
    g_bb4[r * 4 + 1] = make_float4(ca0, ca1, ca2, __int_as_float(seq[r]));
    g_bb4[r * 4 + 2] = make_float4(c0, c1, c2, 0.f);
    g_bb4[r * 4 + 3] = make_float4(cb0, cb1, cb2, 0.f);

    const float* q = rig + (size_t)r * 7;
    float qw = q[0], qx = q[1], qy = q[2], qz = q[3];
    float inv = rsqrtf(qw * qw + qx * qx + qy * qy + qz * qz);
    qw *= inv; qx *= inv; qy *= inv; qz *= inv;

    float R[9];
    R[0] = 1.f - 2.f * (qy * qy + qz * qz);
    R[1] = 2.f * (qx * qy - qw * qz);
    R[2] = 2.f * (qx * qz + qw * qy);
    R[3] = 2.f * (qx * qy + qw * qz);
    R[4] = 1.f - 2.f * (qx * qx + qz * qz);
    R[5] = 2.f * (qy * qz - qw * qx);
    R[6] = 2.f * (qx * qz - qw * qy);
    R[7] = 2.f * (qy * qz + qw * qx);
    R[8] = 1.f - 2.f * (qx * qx + qy * qy);
    float t0 = q[4], t1 = q[5], t2 = q[6];

    // column-major chunks: chunk c = (R[0,c], R[1,c], R[2,c], 0); chunk 3 = t
    g_Rt4[r * 4 + 0] = make_float4(R[0], R[3], R[6], 0.f);
    g_Rt4[r * 4 + 1] = make_float4(R[1], R[4], R[7], 0.f);
    g_Rt4[r * 4 + 2] = make_float4(R[2], R[5], R[8], 0.f);
    g_Rt4[r * 4 + 3] = make_float4(t0, t1, t2, 0.f);

    // local[k][i] = sum_j R[j][i] * (bb[k][j] - t[j])
    #pragma unroll
    for (int k = 0; k < 4; k++) {
        float vx = bb[k * 3 + 0] - t0;
        float vy = bb[k * 3 + 1] - t1;
        float vz = bb[k * 3 + 2] - t2;
        #pragma unroll
        for (int i = 0; i < 3; i++) {
            g_local[r * 12 + k * 3 + i] = R[0 + i] * vx + R[3 + i] * vy + R[6 + i] * vz;
        }
    }
}

// ---------------- per-edge feature kernel: 1 warp / edge, zero smem ----------------
__global__ __launch_bounds__(EPB * 32) void edge_kernel(
    const int* __restrict__ eidx,     // [2, N_EDGE]: row0=dst, row1=src
    float* __restrict__ out) {

    const unsigned FULL = 0xFFFFFFFFu;
    int lane = threadIdx.x & 31;
    int e    = blockIdx.x * EPB + (threadIdx.x >> 5);

    int dst = eidx[e];
    int src = eidx[N_EDGE + e];

    // register gathers (broadcast-heavy, L2-resident tables)
    float4 f4s = g_bb4[src * 4 + ((lane >> 2) & 3)];   // src atom (lane>>2)&3
    float4 f4d = g_bb4[dst * 4 + (lane & 3)];          // dst atom lane&3
    float4 f4rt = g_Rt4[src * 4 + min(max(lane - 4, 0), 3)];  // lanes 4-7: chunks 0-3
    float loc = g_local[src * 12 + min(lane, 11)];     // lanes 0-11 meaningful

    // metadata via shuffle from w-lanes (no extra loads)
    float noised_src = __shfl_sync(FULL, f4s.w, 0);    // lane 0 holds src atom0
    float seqs       = __shfl_sync(FULL, f4s.w, 4);    // lane 4 holds src atom1
    float noised_dst = __shfl_sync(FULL, f4d.w, 0);    // lane 0 holds dst atom0
    float seqd       = __shfl_sync(FULL, f4d.w, 1);    // lane 1 holds dst atom1

    float keep_src = 1.f - noised_src;
    float keep_dst = 1.f - noised_dst;
    int hot_src = __float_as_int(seqs) + 2;    // one-hot pos within row, [2,22]
    int hot_dst = __float_as_int(seqd) + 23;   // one-hot pos within row, [23,43]

    float* __restrict__ row = out + (size_t)e * FEAT;

    // ---- region A: [0..43] flags + one-hots, 11 lanes x STG.128 ----
    if (lane < 11) {
        float4 v4;
        float* vp = &v4.x;
        #pragma unroll
        for (int cc = 0; cc < 4; cc++) {
            int idx = 4 * lane + cc;
            float x = (idx == hot_src) ? keep_src : 0.f;
            x = (idx == hot_dst) ? keep_dst : x;
            vp[cc] = x;
        }
        if (lane == 0) { v4.x = noised_dst; v4.y = noised_src; }
        __stcs((float4*)(row + 4 * lane), v4);
    }

    // ---- region B: [44..299] RBF of 16 dists, 16 bins each ----
    // lanes 0-15 hold src atom (lane>>2) and dst atom (lane&3) in registers:
    // each computes its distance (MUFU.RSQ fast path); two dense STG.128
    // sweeps cover [44..171] and [172..299]. Bins via geometric recurrence.
    float dx = f4s.x - f4d.x + EPSV;
    float dy = f4s.y - f4d.y + EPSV;
    float dz = f4s.z - f4d.z + EPSV;
    float d2 = dx * dx + dy * dy + dz * dz;
    float D = rsqrtf(d2) * d2;              // sqrt via MUFU.RSQ + FMUL

    float mu0 = 2.0f + (float)(4 * (lane & 3)) * (20.0f / 15.0f);
    {
        // sweep 1: lane L -> floats [44+4L..47+4L], pair = L>>2, bins 4*(L&3)..+3
        float Da = __shfl_sync(FULL, D, lane >> 2);
        float z0 = (Da - mu0) * 0.8f;
        float r0 = __expf(-z0 * z0);
        float g  = __expf(fminf(2.0f * RBF_DELTA * z0 - RBF_DSQ, 80.f));
        float r1 = r0 * g; g *= RBF_C;
        float r2 = r1 * g; g *= RBF_C;
        float r3 = r2 * g;
        __stcs((float4*)(row + 44 + 4 * lane), make_float4(r0, r1, r2, r3));

        // sweep 2: lane L -> floats [172+4L..175+4L], pair = 8 + (L>>2)
        float Db = __shfl_sync(FULL, D, 8 + (lane >> 2));
        z0 = (Db - mu0) * 0.8f;
        r0 = __expf(-z0 * z0);
        g  = __expf(fminf(2.0f * RBF_DELTA * z0 - RBF_DSQ, 80.f));
        r1 = r0 * g; g *= RBF_C;
        r2 = r1 * g; g *= RBF_C;
        r3 = r2 * g;
        __stcs((float4*)(row + 172 + 4 * lane), make_float4(r0, r1, r2, r3));
    }

    // ---- region C: [300..315] positional enc (fast sin/cos, HW range red.) ----
    if (lane < 16) {
        float dp = (float)(dst - src);
        float ang = dp * c_freq[lane & 7];
        __stcs(row + 300 + lane, (lane < 8) ? __cosf(ang) : __sinf(ang));
    }

    // ---- regions D+E fused: [316..339] one predicated STG over 24 lanes ----
    // lanes 0..11:  src local frame (prefetched) * keep_src
    // lanes 12..23: dst backbone in src frame * keep_dst, operands via shuffle:
    //   acc = sum_jj R[jj,ii] * (bb_dst[kk][jj] - t[jj])
    //   R[jj,ii] = comp jj of column chunk ii (lane 4+ii)
    //   bb_dst[kk][jj] = comp jj of f4d on lane kk
    //   t[jj] = comp jj of chunk 3 (lane 7)
    {
        int l  = max(lane - 12, 0);
        int kk = min(l / 3, 3);
        int ii = l - 3 * (l / 3);
        float acc = 0.f;
        {   // jj = 0
            float bj = __shfl_sync(FULL, f4d.x, kk);
            float rj = __shfl_sync(FULL, f4rt.x, 4 + ii);
            float tj = __shfl_sync(FULL, f4rt.x, 7);
            acc += rj * (bj - tj);
        }
        {   // jj = 1
            float bj = __shfl_sync(FULL, f4d.y, kk);
            float rj = __shfl_sync(FULL, f4rt.y, 4 + ii);
            float tj = __shfl_sync(FULL, f4rt.y, 7);
            acc += rj * (bj - tj);
        }
        {   // jj = 2
            float bj = __shfl_sync(FULL, f4d.z, kk);
            float rj = __shfl_sync(FULL, f4rt.z, 4 + ii);
            float tj = __shfl_sync(FULL, f4rt.z, 7);
            acc += rj * (bj - tj);
        }
        if (lane < 24) {
            float v = (lane < 12) ? loc * keep_src : acc * keep_dst;
            __stcs(row + 316 + lane, v);
        }
    }
}

// ---------------- launch ----------------
extern "C" void kernel_launch(void* const* d_in, const int* in_sizes, int n_in,
                              void* d_out, int out_size) {
    const float* atom14 = (const float*)d_in[0];
    const float* rigids = (const float*)d_in[1];
    const int*   seq    = (const int*)d_in[2];
    const void*  mask   = d_in[3];
    const int*   eidx   = (const int*)d_in[4];
    float* out = (float*)d_out;

    prep_kernel<<<(N_RES + 255) / 256, 256>>>(atom14, rigids, seq, mask);
    edge_kernel<<<N_EDGE / EPB, EPB * 32>>>(eidx, out);
}